// round 2
// baseline (speedup 1.0000x reference)
#include <cuda_runtime.h>
#include <cuda_bf16.h>
#include <math.h>

// Problem constants
#define NB 8192      // B*N nodes
#define CC 256       // channels
#define EE 131072    // edges
#define BBATCH 8
#define NNODE 1024
#define HHEAD 8
#define DKDIM 32
#define EPS 1e-5f

// ---------------------------------------------------------------------------
// Scratch (single big __device__ buffer; offsets in units of 8192*256 floats)
// ---------------------------------------------------------------------------
#define UNIT (8192*256)
// 0: msg (x@Wn)      1: pre1 (x@Wr + x + agg)   2: h1
// 3: q  4: k  5: v   6: o (attention out)       7: pre2 (o@Wo+bo+x)
// 8: out0 (h1+h2)    9: out1 (out0 + mlp)       10-11: hidden [8192,512]
__device__ float g_buf[12 * UNIT + 1024];
#define STATS_OFF (12 * UNIT)   // 512 floats: sum[256], sumsq[256]

// Sanitized edge indices (int32) + dtype-detect flag
__device__ int g_ei32[2 * EE];
__device__ int g_is64;

// ---------------------------------------------------------------------------
// Edge-index dtype detection + conversion (robust to int32 or int64 input)
// ---------------------------------------------------------------------------
__global__ void ei_detect_kernel(const int* __restrict__ raw)
{
    // If the buffer is int64 (little-endian, values in [0, 8192)), every odd
    // int32 word is the zero high-word. For genuine int32 data these are
    // random src indices; 256 of them all being zero has prob ~(1/8192)^256.
    __shared__ int nz;
    if (threadIdx.x == 0) nz = 0;
    __syncthreads();
    int vodd = raw[2 * threadIdx.x + 1];
    if (vodd != 0) atomicAdd(&nz, 1);
    __syncthreads();
    if (threadIdx.x == 0) g_is64 = (nz == 0) ? 1 : 0;
}

__global__ void ei_convert_kernel(const void* __restrict__ raw)
{
    int i = blockIdx.x * blockDim.x + threadIdx.x;   // 0 .. 2*EE-1
    if (i >= 2 * EE) return;
    int v;
    if (g_is64) v = (int)((const long long*)raw)[i];
    else        v = ((const int*)raw)[i];
    v = min(max(v, 0), NB - 1);                      // never fault
    g_ei32[i] = v;
}

// ---------------------------------------------------------------------------
// SGEMM: Y[M,N] = X[M,K] @ W[K,N] (+bias) (+add) (relu?)
// 128x128 tile, BK=8, 256 threads, 8x8 per thread
// ---------------------------------------------------------------------------
__global__ __launch_bounds__(256) void sgemm_kernel(
    const float* __restrict__ X, const float* __restrict__ W,
    const float* __restrict__ bias, const float* __restrict__ add,
    float* __restrict__ Y, int M, int N, int K, int relu)
{
    __shared__ float Xs[8][128];
    __shared__ float Ws[8][128];
    int tid = threadIdx.x;
    int tx = tid & 15, ty = tid >> 4;
    int row0 = blockIdx.y * 128, col0 = blockIdx.x * 128;

    float acc[8][8];
#pragma unroll
    for (int i = 0; i < 8; i++)
#pragma unroll
        for (int j = 0; j < 8; j++) acc[i][j] = 0.f;

    int lm = tid >> 1;            // 0..127 row for X load
    int lh = (tid & 1) * 4;       // k-offset 0 or 4
    int lk = tid >> 5;            // 0..7 k for W load
    int ln = (tid & 31) * 4;      // 0..124 col for W load

    for (int k0 = 0; k0 < K; k0 += 8) {
        float4 xa = *reinterpret_cast<const float4*>(&X[(size_t)(row0 + lm) * K + k0 + lh]);
        Xs[lh + 0][lm] = xa.x; Xs[lh + 1][lm] = xa.y;
        Xs[lh + 2][lm] = xa.z; Xs[lh + 3][lm] = xa.w;
        *reinterpret_cast<float4*>(&Ws[lk][ln]) =
            *reinterpret_cast<const float4*>(&W[(size_t)(k0 + lk) * N + col0 + ln]);
        __syncthreads();
#pragma unroll
        for (int kk = 0; kk < 8; kk++) {
            float a[8], b[8];
            *(float4*)&a[0] = *(const float4*)&Xs[kk][ty * 4];
            *(float4*)&a[4] = *(const float4*)&Xs[kk][64 + ty * 4];
            *(float4*)&b[0] = *(const float4*)&Ws[kk][tx * 4];
            *(float4*)&b[4] = *(const float4*)&Ws[kk][64 + tx * 4];
#pragma unroll
            for (int i = 0; i < 8; i++)
#pragma unroll
                for (int j = 0; j < 8; j++) acc[i][j] += a[i] * b[j];
        }
        __syncthreads();
    }

#pragma unroll
    for (int i = 0; i < 8; i++) {
        int r = row0 + ((i < 4) ? (ty * 4 + i) : (64 + ty * 4 + i - 4));
#pragma unroll
        for (int j = 0; j < 8; j++) {
            int c = col0 + ((j < 4) ? (tx * 4 + j) : (64 + tx * 4 + j - 4));
            float v = acc[i][j];
            if (bias) v += bias[c];
            if (add)  v += add[(size_t)r * N + c];
            if (relu) v = fmaxf(v, 0.f);
            Y[(size_t)r * N + c] = v;
        }
    }
}

// ---------------------------------------------------------------------------
// Edge scatter: pre1[dst, :] += msg[src, :]
// 256 threads handle one edge's 256 channels; 4 edges per block.
// ---------------------------------------------------------------------------
__global__ __launch_bounds__(256) void scatter_kernel(const float* __restrict__ msg,
                                                      float* __restrict__ out)
{
    int c = threadIdx.x;
#pragma unroll
    for (int u = 0; u < 4; u++) {
        int e = blockIdx.x * 4 + u;
        int s = g_ei32[e];
        int d = g_ei32[EE + e];
        atomicAdd(&out[(size_t)d * CC + c], msg[(size_t)s * CC + c]);
    }
}

// ---------------------------------------------------------------------------
// BatchNorm: stats (sum/sumsq per channel) + apply
// ---------------------------------------------------------------------------
__global__ void zero_stats_kernel(float* stats) { stats[threadIdx.x] = 0.f; }

__global__ void bn_stats_kernel(const float* __restrict__ X, float* __restrict__ stats)
{
    int c = threadIdx.x;                 // 256 channels
    int r0 = blockIdx.x * 256;           // 32 blocks
    float s = 0.f, ss = 0.f;
    for (int r = 0; r < 256; r++) {
        float v = X[(size_t)(r0 + r) * CC + c];
        s += v; ss += v * v;
    }
    atomicAdd(&stats[c], s);
    atomicAdd(&stats[CC + c], ss);
}

__global__ void bn_apply_kernel(const float* __restrict__ X,
                                const float* __restrict__ stats,
                                const float* __restrict__ gamma,
                                const float* __restrict__ beta,
                                const float* __restrict__ add,
                                float* __restrict__ Y)
{
    int r = blockIdx.x;                  // 8192 rows
    int c = threadIdx.x;                 // 256 channels
    float mean = stats[c] * (1.f / NB);
    float var = stats[CC + c] * (1.f / NB) - mean * mean;
    float inv = rsqrtf(var + EPS);
    size_t idx = (size_t)r * CC + c;
    float v = (X[idx] - mean) * inv * gamma[c] + beta[c];
    if (add) v += add[idx];
    Y[idx] = v;
}

// ---------------------------------------------------------------------------
// Flash attention with sph modulation.
// grid = B*H*(N/64); block = 256. Each CTA: 64 queries, one head, streams 16
// key tiles of 64. Thread (row=tid/4, j=tid%4) owns 16 keys of the S row,
// full 32-dim acc; final cross-reduce over the 4 row-threads via shfl.
// ---------------------------------------------------------------------------
#define QT 64
#define KT 64
#define KS_STRIDE 36   // 32 + 4 pad (float4-friendly, conflict-free)
#define SP_STRIDE 65

__global__ __launch_bounds__(256) void attn_kernel(
    const float* __restrict__ q, const float* __restrict__ k,
    const float* __restrict__ v, const float* __restrict__ sph,
    float* __restrict__ o)
{
    __shared__ float ks[KT * KS_STRIDE];
    __shared__ float vs[KT * KS_STRIDE];
    __shared__ float sp[QT * SP_STRIDE];
    __shared__ float qs[QT * KS_STRIDE];

    const int qtiles = NNODE / QT;           // 16
    int bh = blockIdx.x / qtiles;
    int qt = blockIdx.x % qtiles;
    int b = bh / HHEAD;
    int h = bh % HHEAD;
    int row0 = qt * QT;                      // within batch
    int tid = threadIdx.x;
    const float scale = 0.17677669529663687f; // 1/sqrt(32)

    // load q tile (scaled) into smem, then thread's row into regs
#pragma unroll
    for (int it = 0; it < 8; it++) {
        int idx = tid + it * 256;            // 0..2047
        int r = idx >> 5, d = idx & 31;
        qs[r * KS_STRIDE + d] =
            q[(size_t)(b * NNODE + row0 + r) * CC + h * DKDIM + d] * scale;
    }
    __syncthreads();

    int row = tid >> 2;
    int j = tid & 3;

    float4 q4[8];
    {
        const float4* qp = reinterpret_cast<const float4*>(&qs[row * KS_STRIDE]);
#pragma unroll
        for (int i = 0; i < 8; i++) q4[i] = qp[i];
    }

    float4 acc4[8];
#pragma unroll
    for (int i = 0; i < 8; i++) acc4[i] = make_float4(0.f, 0.f, 0.f, 0.f);
    float mrun = -INFINITY, lrun = 0.f;

    for (int kt = 0; kt < NNODE / KT; kt++) {
        __syncthreads();
#pragma unroll
        for (int it = 0; it < 8; it++) {
            int idx = tid + it * 256;
            int r = idx >> 5, d = idx & 31;
            size_t g = (size_t)(b * NNODE + kt * KT + r) * CC + h * DKDIM + d;
            ks[r * KS_STRIDE + d] = k[g];
            vs[r * KS_STRIDE + d] = v[g];
        }
#pragma unroll
        for (int it = 0; it < 16; it++) {
            int idx = tid + it * 256;        // 0..4095
            int qr = idx >> 6, kc = idx & 63;
            sp[qr * SP_STRIDE + kc] =
                sph[(size_t)(b * NNODE + row0 + qr) * NNODE + kt * KT + kc];
        }
        __syncthreads();

        float sr[16];
        float tmax = -INFINITY;
#pragma unroll
        for (int t = 0; t < 16; t++) {
            int m = j * 16 + t;
            const float4* k4 = reinterpret_cast<const float4*>(&ks[m * KS_STRIDE]);
            float dot = 0.f;
#pragma unroll
            for (int i = 0; i < 8; i++) {
                float4 kv = k4[i];
                dot += q4[i].x * kv.x + q4[i].y * kv.y + q4[i].z * kv.z + q4[i].w * kv.w;
            }
            float s = dot * sp[row * SP_STRIDE + m];
            sr[t] = s;
            tmax = fmaxf(tmax, s);
        }
        tmax = fmaxf(tmax, __shfl_xor_sync(0xffffffff, tmax, 1));
        tmax = fmaxf(tmax, __shfl_xor_sync(0xffffffff, tmax, 2));

        float mnew = fmaxf(mrun, tmax);
        float corr = __expf(mrun - mnew);
        float lsum = 0.f;
#pragma unroll
        for (int t = 0; t < 16; t++) {
            float p = __expf(sr[t] - mnew);
            sr[t] = p;
            lsum += p;
        }
        lsum += __shfl_xor_sync(0xffffffff, lsum, 1);
        lsum += __shfl_xor_sync(0xffffffff, lsum, 2);
        lrun = lrun * corr + lsum;
        mrun = mnew;

#pragma unroll
        for (int i = 0; i < 8; i++) {
            acc4[i].x *= corr; acc4[i].y *= corr;
            acc4[i].z *= corr; acc4[i].w *= corr;
        }
#pragma unroll
        for (int t = 0; t < 16; t++) {
            float p = sr[t];
            int m = j * 16 + t;
            const float4* v4 = reinterpret_cast<const float4*>(&vs[m * KS_STRIDE]);
#pragma unroll
            for (int i = 0; i < 8; i++) {
                float4 vv = v4[i];
                acc4[i].x += p * vv.x; acc4[i].y += p * vv.y;
                acc4[i].z += p * vv.z; acc4[i].w += p * vv.w;
            }
        }
    }

    // reduce acc across the 4 threads of a row
    float accf[32];
#pragma unroll
    for (int i = 0; i < 8; i++) {
        accf[i * 4 + 0] = acc4[i].x; accf[i * 4 + 1] = acc4[i].y;
        accf[i * 4 + 2] = acc4[i].z; accf[i * 4 + 3] = acc4[i].w;
    }
#pragma unroll
    for (int d = 0; d < 32; d++) {
        accf[d] += __shfl_xor_sync(0xffffffff, accf[d], 1);
        accf[d] += __shfl_xor_sync(0xffffffff, accf[d], 2);
    }
    float inv = 1.f / lrun;
    size_t base = (size_t)(b * NNODE + row0 + row) * CC + h * DKDIM;
#pragma unroll
    for (int dd = 0; dd < 8; dd++)
        o[base + j * 8 + dd] = accf[j * 8 + dd] * inv;
}

// ---------------------------------------------------------------------------
// Launch
// ---------------------------------------------------------------------------
extern "C" void kernel_launch(void* const* d_in, const int* in_sizes, int n_in,
                              void* d_out, int out_size)
{
    const float* x   = (const float*)d_in[0];
    const void*  ei  = d_in[1];                 // int32 or int64, auto-detected
    const float* sph = (const float*)d_in[2];
    const float* Wr  = (const float*)d_in[3];
    const float* Wn  = (const float*)d_in[4];
    const float* Wq  = (const float*)d_in[5];
    const float* bq  = (const float*)d_in[6];
    const float* Wk  = (const float*)d_in[7];
    const float* bk  = (const float*)d_in[8];
    const float* Wv  = (const float*)d_in[9];
    const float* bv  = (const float*)d_in[10];
    const float* Wo  = (const float*)d_in[11];
    const float* bo  = (const float*)d_in[12];
    const float* W1  = (const float*)d_in[13];
    const float* b1  = (const float*)d_in[14];
    const float* W2  = (const float*)d_in[15];
    const float* b2  = (const float*)d_in[16];
    const float* g1  = (const float*)d_in[17];
    const float* be1 = (const float*)d_in[18];
    const float* g2  = (const float*)d_in[19];
    const float* be2 = (const float*)d_in[20];
    const float* g3  = (const float*)d_in[21];
    const float* be3 = (const float*)d_in[22];
    float* out = (float*)d_out;

    float* buf = nullptr;
    cudaGetSymbolAddress((void**)&buf, g_buf);
    float* g_msg    = buf + 0 * (size_t)UNIT;
    float* g_pre1   = buf + 1 * (size_t)UNIT;
    float* g_h1     = buf + 2 * (size_t)UNIT;
    float* g_q      = buf + 3 * (size_t)UNIT;
    float* g_k      = buf + 4 * (size_t)UNIT;
    float* g_v      = buf + 5 * (size_t)UNIT;
    float* g_o      = buf + 6 * (size_t)UNIT;
    float* g_pre2   = buf + 7 * (size_t)UNIT;
    float* g_out0   = buf + 8 * (size_t)UNIT;
    float* g_out1   = buf + 9 * (size_t)UNIT;
    float* g_hidden = buf + 10 * (size_t)UNIT;
    float* g_stats  = buf + STATS_OFF;

    dim3 blk(256);
    dim3 g256(CC / 128, NB / 128);   // N=256
    dim3 g512(512 / 128, NB / 128);  // N=512

    // 0) sanitize edge indices (dtype-robust)
    ei_detect_kernel<<<1, 256>>>((const int*)ei);
    ei_convert_kernel<<<(2 * EE + 255) / 256, 256>>>(ei);

    // 1) local branch: msg = x@Wn ; pre1 = x@Wr + x ; pre1 += scatter(msg)
    sgemm_kernel<<<g256, blk>>>(x, Wn, nullptr, nullptr, g_msg, NB, CC, CC, 0);
    sgemm_kernel<<<g256, blk>>>(x, Wr, nullptr, x, g_pre1, NB, CC, CC, 0);
    scatter_kernel<<<EE / 4, 256>>>(g_msg, g_pre1);
    zero_stats_kernel<<<1, 512>>>(g_stats);
    bn_stats_kernel<<<NB / 256, 256>>>(g_pre1, g_stats);
    bn_apply_kernel<<<NB, 256>>>(g_pre1, g_stats, g1, be1, nullptr, g_h1);

    // 2) attention branch
    sgemm_kernel<<<g256, blk>>>(x, Wq, bq, nullptr, g_q, NB, CC, CC, 0);
    sgemm_kernel<<<g256, blk>>>(x, Wk, bk, nullptr, g_k, NB, CC, CC, 0);
    sgemm_kernel<<<g256, blk>>>(x, Wv, bv, nullptr, g_v, NB, CC, CC, 0);
    attn_kernel<<<BBATCH * HHEAD * (NNODE / QT), 256>>>(g_q, g_k, g_v, sph, g_o);
    sgemm_kernel<<<g256, blk>>>(g_o, Wo, bo, x, g_pre2, NB, CC, CC, 0);
    zero_stats_kernel<<<1, 512>>>(g_stats);
    bn_stats_kernel<<<NB / 256, 256>>>(g_pre2, g_stats);
    // out0 = h1 + bn(pre2)
    bn_apply_kernel<<<NB, 256>>>(g_pre2, g_stats, g2, be2, g_h1, g_out0);

    // 3) MLP residual + norm3
    sgemm_kernel<<<g512, blk>>>(g_out0, W1, b1, nullptr, g_hidden, NB, 512, CC, 1);
    sgemm_kernel<<<g256, blk>>>(g_hidden, W2, b2, g_out0, g_out1, NB, CC, 512, 0);
    zero_stats_kernel<<<1, 512>>>(g_stats);
    bn_stats_kernel<<<NB / 256, 256>>>(g_out1, g_stats);
    bn_apply_kernel<<<NB, 256>>>(g_out1, g_stats, g3, be3, nullptr, out);
}

// round 4
// speedup vs baseline: 3.5106x; 3.5106x over previous
#include <cuda_runtime.h>
#include <cuda_bf16.h>
#include <math.h>

#define NB 8192
#define CC 256
#define EE 131072
#define BBATCH 8
#define NNODE 1024
#define HHEAD 8
#define DKDIM 32
#define EPS 1e-5f

typedef unsigned long long ULL;

// ---------------------------------------------------------------------------
// Scratch
// ---------------------------------------------------------------------------
#define UNIT (8192*256)
// u0-1: mp = [msg | pre1]  (8192 x 512)
// u2:   h1
// u3-5: qkv (8192 x 768)
// u6:   o
// u7:   pre2
// u8:   out0
// u9:   out1
// u10-11: hidden (8192 x 512)
#define TAIL (12*UNIT)
__device__ float g_buf[12 * UNIT + 331264];
// tail: wrn 131072 @ TAIL ; wqkv 196608 @ TAIL+131072 ; bqkv @ TAIL+327680
// stats 3*512 @ TAIL+328704
#define OFF_WRN   (TAIL)
#define OFF_WQKV  (TAIL + 131072)
#define OFF_BQKV  (TAIL + 327680)
#define OFF_STATS (TAIL + 328704)

__device__ int g_ei32[2 * EE];
__device__ int g_is64;

// ---------------------------------------------------------------------------
// f32x2 helpers
// ---------------------------------------------------------------------------
__device__ __forceinline__ ULL pk(float a, float b) {
    ULL r; asm("mov.b64 %0, {%1,%2};" : "=l"(r) : "f"(a), "f"(b)); return r;
}
__device__ __forceinline__ ULL d2(float a) {
    ULL r; asm("mov.b64 %0, {%1,%1};" : "=l"(r) : "f"(a)); return r;
}
__device__ __forceinline__ float2 up(ULL a) {
    float2 r; asm("mov.b64 {%0,%1}, %2;" : "=f"(r.x), "=f"(r.y) : "l"(a)); return r;
}
__device__ __forceinline__ ULL f2(ULL a, ULL b, ULL c) {
    ULL d; asm("fma.rn.f32x2 %0, %1, %2, %3;" : "=l"(d) : "l"(a), "l"(b), "l"(c)); return d;
}
__device__ __forceinline__ ULL m2(ULL a, ULL b) {
    ULL d; asm("mul.rn.f32x2 %0, %1, %2;" : "=l"(d) : "l"(a), "l"(b)); return d;
}
__device__ __forceinline__ ULL a2(ULL a, ULL b) {
    ULL d; asm("add.rn.f32x2 %0, %1, %2;" : "=l"(d) : "l"(a), "l"(b)); return d;
}

// fast exp via 2^n * poly(f), all on fma/alu pipes (no MUFU)
__device__ __forceinline__ float fexp(float x) {
    x = fmaxf(x, -80.f);
    float y = x * 1.4426950408889634f;
    float z = y + 12582912.f;          // round-to-nearest trick
    int ni = __float_as_int(z);
    float nf = z - 12582912.f;
    float t = (y - nf) * 0.6931471805599453f;   // |t| <= 0.347
    float p = 1.f + t * (1.f + t * (0.5f + t * (0.16666667f + t * (0.041666667f + t * 0.0083333333f))));
    float sc = __int_as_float((ni + 127) << 23);
    return p * sc;
}

// ---------------------------------------------------------------------------
// Edge-index dtype detection + conversion
// ---------------------------------------------------------------------------
__global__ void ei_detect_kernel(const int* __restrict__ raw)
{
    __shared__ int nz;
    if (threadIdx.x == 0) nz = 0;
    __syncthreads();
    if (raw[2 * threadIdx.x + 1] != 0) atomicAdd(&nz, 1);
    __syncthreads();
    if (threadIdx.x == 0) g_is64 = (nz == 0) ? 1 : 0;
}

__global__ void ei_convert_kernel(const void* __restrict__ raw)
{
    int i = blockIdx.x * blockDim.x + threadIdx.x;
    if (i >= 2 * EE) return;
    int v;
    if (g_is64) v = (int)((const long long*)raw)[i];
    else        v = ((const int*)raw)[i];
    g_ei32[i] = min(max(v, 0), NB - 1);
}

// ---------------------------------------------------------------------------
// Weight concat kernels
// ---------------------------------------------------------------------------
__global__ void wcat_rn_kernel(const float* __restrict__ Wn, const float* __restrict__ Wr,
                               float* __restrict__ W)
{
    int idx = blockIdx.x * 256 + threadIdx.x;   // 0..131071
    int r = idx >> 9, c = idx & 511;
    W[idx] = (c < 256) ? Wn[r * 256 + c] : Wr[r * 256 + (c - 256)];
}

__global__ void wcat_qkv_kernel(const float* __restrict__ Wq, const float* __restrict__ Wk,
                                const float* __restrict__ Wv,
                                const float* __restrict__ bq, const float* __restrict__ bk,
                                const float* __restrict__ bv,
                                float* __restrict__ W, float* __restrict__ bvec)
{
    int idx = blockIdx.x * 256 + threadIdx.x;   // 0..196607
    int r = idx / 768, c = idx % 768;
    int sel = c >> 8, cc = c & 255;
    const float* src = (sel == 0) ? Wq : (sel == 1) ? Wk : Wv;
    W[idx] = src[r * 256 + cc];
    if (idx < 768) {
        const float* bs = (sel == 0) ? bq : (sel == 1) ? bk : bv;
        // careful: for idx<768, r==0 so c==idx
        bvec[idx] = bs[idx & 255];
    }
}

__global__ void zero_stats_kernel(float* stats) {
    stats[blockIdx.x * 256 + threadIdx.x] = 0.f;   // grid 6 -> 1536 floats
}

// ---------------------------------------------------------------------------
// SGEMM with f32x2 + double buffering. 128x128 tile, BK=8, 256 threads.
// ---------------------------------------------------------------------------
__global__ __launch_bounds__(256) void sgemm2(
    const float* __restrict__ X, const float* __restrict__ W,
    const float* __restrict__ bias, const float* __restrict__ add,
    int addOff, int addStride,
    float* __restrict__ Y, int M, int N, int K, int relu)
{
    __shared__ float Xs[2][8][128];
    __shared__ float Ws[2][8][128];
    int tid = threadIdx.x;
    int tx = tid & 15, ty = tid >> 4;
    int row0 = blockIdx.y * 128, col0 = blockIdx.x * 128;

    int lm = tid >> 1, lh = (tid & 1) * 4;
    int lk = tid >> 5, ln = (tid & 31) * 4;
    const float* Xp = X + (size_t)(row0 + lm) * K + lh;
    const float* Wp = W + (size_t)lk * N + col0 + ln;

    ULL acc[8][4];
#pragma unroll
    for (int i = 0; i < 8; i++)
#pragma unroll
        for (int j = 0; j < 4; j++) acc[i][j] = 0ULL;

    // prologue load
    {
        float4 xa = *(const float4*)(Xp);
        Xs[0][lh + 0][lm] = xa.x; Xs[0][lh + 1][lm] = xa.y;
        Xs[0][lh + 2][lm] = xa.z; Xs[0][lh + 3][lm] = xa.w;
        *(float4*)&Ws[0][lk][ln] = *(const float4*)(Wp);
    }
    __syncthreads();

    int buf = 0;
    for (int k0 = 0; k0 < K; k0 += 8) {
        if (k0 + 8 < K) {
            float4 xa = *(const float4*)(Xp + k0 + 8);
            Xs[buf ^ 1][lh + 0][lm] = xa.x; Xs[buf ^ 1][lh + 1][lm] = xa.y;
            Xs[buf ^ 1][lh + 2][lm] = xa.z; Xs[buf ^ 1][lh + 3][lm] = xa.w;
            *(float4*)&Ws[buf ^ 1][lk][ln] = *(const float4*)(Wp + (size_t)(k0 + 8) * N);
        }
#pragma unroll
        for (int kk = 0; kk < 8; kk++) {
            float4 a0 = *(const float4*)&Xs[buf][kk][ty * 4];
            float4 a1 = *(const float4*)&Xs[buf][kk][64 + ty * 4];
            float4 b0 = *(const float4*)&Ws[buf][kk][tx * 4];
            float4 b1 = *(const float4*)&Ws[buf][kk][64 + tx * 4];
            ULL bp0 = pk(b0.x, b0.y), bp1 = pk(b0.z, b0.w);
            ULL bp2 = pk(b1.x, b1.y), bp3 = pk(b1.z, b1.w);
            float av[8] = {a0.x, a0.y, a0.z, a0.w, a1.x, a1.y, a1.z, a1.w};
#pragma unroll
            for (int i = 0; i < 8; i++) {
                ULL ad = d2(av[i]);
                acc[i][0] = f2(ad, bp0, acc[i][0]);
                acc[i][1] = f2(ad, bp1, acc[i][1]);
                acc[i][2] = f2(ad, bp2, acc[i][2]);
                acc[i][3] = f2(ad, bp3, acc[i][3]);
            }
        }
        __syncthreads();
        buf ^= 1;
    }

#pragma unroll
    for (int i = 0; i < 8; i++) {
        int r = row0 + ((i < 4) ? (ty * 4 + i) : (64 + ty * 4 + i - 4));
#pragma unroll
        for (int jp = 0; jp < 4; jp++) {
            int c = col0 + ((jp < 2) ? (tx * 4 + jp * 2) : (64 + tx * 4 + (jp - 2) * 2));
            float2 t = up(acc[i][jp]);
            float v0 = t.x, v1 = t.y;
            if (bias) { v0 += bias[c]; v1 += bias[c + 1]; }
            if (add && c >= addOff) {
                v0 += add[(size_t)r * addStride + (c - addOff)];
                v1 += add[(size_t)r * addStride + (c + 1 - addOff)];
            }
            if (relu) { v0 = fmaxf(v0, 0.f); v1 = fmaxf(v1, 0.f); }
            *(float2*)&Y[(size_t)r * N + c] = make_float2(v0, v1);
        }
    }
}

// ---------------------------------------------------------------------------
// Edge scatter: mp[dst, 256+c] += mp[src, c]  (fused buffer, stride 512)
// ---------------------------------------------------------------------------
__global__ __launch_bounds__(256) void scatter2(float* __restrict__ mp)
{
    int u = threadIdx.x >> 6;
    int c4 = (threadIdx.x & 63) * 4;
    int e = blockIdx.x * 4 + u;
    int s = g_ei32[e], d = g_ei32[EE + e];
    float4 v = *(const float4*)&mp[(size_t)s * 512 + c4];
    float* p = &mp[(size_t)d * 512 + 256 + c4];
    asm volatile("red.global.add.v4.f32 [%0], {%1,%2,%3,%4};"
                 :: "l"(p), "f"(v.x), "f"(v.y), "f"(v.z), "f"(v.w) : "memory");
}

// ---------------------------------------------------------------------------
// BatchNorm stats: 128 blocks x 64 rows, float4, smem tree, then atomics
// ---------------------------------------------------------------------------
__global__ __launch_bounds__(256) void bn_stats2(const float* __restrict__ X,
                                                 int stride, int coloff,
                                                 float* __restrict__ stats)
{
    __shared__ float4 rs[4][64], rq[4][64];
    int tid = threadIdx.x;
    int cg = tid & 63, g = tid >> 6;
    int c4 = cg * 4;
    int r0 = blockIdx.x * 64;
    float4 s = make_float4(0, 0, 0, 0), q = make_float4(0, 0, 0, 0);
    for (int r = g; r < 64; r += 4) {
        float4 v = *(const float4*)&X[(size_t)(r0 + r) * stride + coloff + c4];
        s.x += v.x; s.y += v.y; s.z += v.z; s.w += v.w;
        q.x += v.x * v.x; q.y += v.y * v.y; q.z += v.z * v.z; q.w += v.w * v.w;
    }
    rs[g][cg] = s; rq[g][cg] = q;
    __syncthreads();
    if (g == 0) {
        float4 S = rs[0][cg], Q = rq[0][cg];
#pragma unroll
        for (int i = 1; i < 4; i++) {
            float4 a = rs[i][cg], b = rq[i][cg];
            S.x += a.x; S.y += a.y; S.z += a.z; S.w += a.w;
            Q.x += b.x; Q.y += b.y; Q.z += b.z; Q.w += b.w;
        }
        atomicAdd(&stats[c4 + 0], S.x); atomicAdd(&stats[c4 + 1], S.y);
        atomicAdd(&stats[c4 + 2], S.z); atomicAdd(&stats[c4 + 3], S.w);
        atomicAdd(&stats[256 + c4 + 0], Q.x); atomicAdd(&stats[256 + c4 + 1], Q.y);
        atomicAdd(&stats[256 + c4 + 2], Q.z); atomicAdd(&stats[256 + c4 + 3], Q.w);
    }
}

__global__ __launch_bounds__(256) void bn_apply2(const float* __restrict__ X,
                                                 int stride, int coloff,
                                                 const float* __restrict__ stats,
                                                 const float* __restrict__ gamma,
                                                 const float* __restrict__ beta,
                                                 const float* __restrict__ add,
                                                 float* __restrict__ Y)
{
    int idx = blockIdx.x * 256 + threadIdx.x;   // one float4 of [8192,256]
    int r = idx >> 6, c4 = (idx & 63) * 4;
    float4 v = *(const float4*)&X[(size_t)r * stride + coloff + c4];
    float4 S = *(const float4*)&stats[c4];
    float4 Q = *(const float4*)&stats[256 + c4];
    float4 G = *(const float4*)&gamma[c4];
    float4 Bt = *(const float4*)&beta[c4];
    const float invN = 1.f / NB;
    float m0 = S.x * invN, m1 = S.y * invN, m2v = S.z * invN, m3 = S.w * invN;
    float i0 = rsqrtf(Q.x * invN - m0 * m0 + EPS);
    float i1 = rsqrtf(Q.y * invN - m1 * m1 + EPS);
    float i2 = rsqrtf(Q.z * invN - m2v * m2v + EPS);
    float i3 = rsqrtf(Q.w * invN - m3 * m3 + EPS);
    float4 o;
    o.x = (v.x - m0) * i0 * G.x + Bt.x;
    o.y = (v.y - m1) * i1 * G.y + Bt.y;
    o.z = (v.z - m2v) * i2 * G.z + Bt.z;
    o.w = (v.w - m3) * i3 * G.w + Bt.w;
    if (add) {
        float4 a = *(const float4*)&add[(size_t)r * 256 + c4];
        o.x += a.x; o.y += a.y; o.z += a.z; o.w += a.w;
    }
    *(float4*)&Y[(size_t)r * 256 + c4] = o;
}

// ---------------------------------------------------------------------------
// Attention: 64Q x 64K tiles, outer-product QK (transposed q/k in smem),
// P via smem, key-split PV, f32x2 + polynomial exp.
// ---------------------------------------------------------------------------
#define QTS 68
#define VST 36
#define SPS 68

__global__ __launch_bounds__(256, 2) void attn2(const float* __restrict__ qkv,
                                                const float* __restrict__ sph,
                                                float* __restrict__ o)
{
    __shared__ float qt[32 * QTS];
    __shared__ float ktile[32 * QTS];
    __shared__ float vsm[64 * VST];
    __shared__ float spm[64 * SPS];   // also used as Pt

    int tid = threadIdx.x;
    int bh = blockIdx.x >> 4;
    int qti = blockIdx.x & 15;
    int b = bh >> 3, h = bh & 7;
    int row0 = qti * 64;
    const float scale = 0.17677669529663687f;

    // ---- load q transposed (scaled) ----
    {
        int r = tid >> 2, cq = tid & 3;
        const float* qrow = qkv + (size_t)(b * NNODE + row0 + r) * 768 + h * 32 + cq * 8;
        float4 qa = *(const float4*)qrow;
        float4 qb = *(const float4*)(qrow + 4);
        int d0 = cq * 8;
        qt[(d0 + 0) * QTS + r] = qa.x * scale; qt[(d0 + 1) * QTS + r] = qa.y * scale;
        qt[(d0 + 2) * QTS + r] = qa.z * scale; qt[(d0 + 3) * QTS + r] = qa.w * scale;
        qt[(d0 + 4) * QTS + r] = qb.x * scale; qt[(d0 + 5) * QTS + r] = qb.y * scale;
        qt[(d0 + 6) * QTS + r] = qb.z * scale; qt[(d0 + 7) * QTS + r] = qb.w * scale;
    }

    int ty = tid >> 4, tx = tid & 15;       // S ownership: rows ty*4.., cols tx*4..
    int dg = tid & 3, ksub = (tid >> 2) & 3; // PV ownership: d0 = dg*8, keys 4t+ksub
    int d0v = dg * 8;

    float m[4], l[4];
#pragma unroll
    for (int i = 0; i < 4; i++) { m[i] = -INFINITY; l[i] = 0.f; }
    ULL accO[4][4];
#pragma unroll
    for (int i = 0; i < 4; i++)
#pragma unroll
        for (int p = 0; p < 4; p++) accO[i][p] = 0ULL;

    for (int kt0 = 0; kt0 < NNODE; kt0 += 64) {
        __syncthreads();
        // ---- load k (transposed) and v (row-major) ----
        {
            int r = tid >> 2, cq = tid & 3;
            const float* krow = qkv + (size_t)(b * NNODE + kt0 + r) * 768 + 256 + h * 32 + cq * 8;
            float4 ka = *(const float4*)krow;
            float4 kb = *(const float4*)(krow + 4);
            int d0 = cq * 8;
            ktile[(d0 + 0) * QTS + r] = ka.x; ktile[(d0 + 1) * QTS + r] = ka.y;
            ktile[(d0 + 2) * QTS + r] = ka.z; ktile[(d0 + 3) * QTS + r] = ka.w;
            ktile[(d0 + 4) * QTS + r] = kb.x; ktile[(d0 + 5) * QTS + r] = kb.y;
            ktile[(d0 + 6) * QTS + r] = kb.z; ktile[(d0 + 7) * QTS + r] = kb.w;
            const float* vrow = qkv + (size_t)(b * NNODE + kt0 + r) * 768 + 512 + h * 32 + cq * 8;
            *(float4*)&vsm[r * VST + cq * 8]     = *(const float4*)vrow;
            *(float4*)&vsm[r * VST + cq * 8 + 4] = *(const float4*)(vrow + 4);
        }
        // ---- load sph tile ----
#pragma unroll
        for (int it = 0; it < 4; it++) {
            int idx = it * 256 + tid;          // 1024 float4s
            int qr = idx >> 4, kc4 = (idx & 15) * 4;
            *(float4*)&spm[qr * SPS + kc4] =
                *(const float4*)&sph[((size_t)(b * NNODE + row0 + qr)) * NNODE + kt0 + kc4];
        }
        __syncthreads();

        // ---- QK outer product ----
        ULL s2[4][2];
#pragma unroll
        for (int i = 0; i < 4; i++) { s2[i][0] = 0ULL; s2[i][1] = 0ULL; }
#pragma unroll 8
        for (int d = 0; d < 32; d++) {
            float4 q4 = *(const float4*)&qt[d * QTS + ty * 4];
            float4 k4 = *(const float4*)&ktile[d * QTS + tx * 4];
            ULL k01 = pk(k4.x, k4.y), k23 = pk(k4.z, k4.w);
            float qv[4] = {q4.x, q4.y, q4.z, q4.w};
#pragma unroll
            for (int i = 0; i < 4; i++) {
                ULL qd = d2(qv[i]);
                s2[i][0] = f2(qd, k01, s2[i][0]);
                s2[i][1] = f2(qd, k23, s2[i][1]);
            }
        }

        // ---- modulate by sph, online softmax ----
        float p[4][4], mt[4];
#pragma unroll
        for (int i = 0; i < 4; i++) {
            float4 sp4 = *(const float4*)&spm[(ty * 4 + i) * SPS + tx * 4];
            float2 ua = up(s2[i][0]), ub = up(s2[i][1]);
            p[i][0] = ua.x * sp4.x; p[i][1] = ua.y * sp4.y;
            p[i][2] = ub.x * sp4.z; p[i][3] = ub.y * sp4.w;
            mt[i] = fmaxf(fmaxf(p[i][0], p[i][1]), fmaxf(p[i][2], p[i][3]));
        }
#pragma unroll
        for (int mask = 1; mask < 16; mask <<= 1)
#pragma unroll
            for (int i = 0; i < 4; i++)
                mt[i] = fmaxf(mt[i], __shfl_xor_sync(0xffffffff, mt[i], mask));
#pragma unroll
        for (int i = 0; i < 4; i++) {
            float mn = fmaxf(m[i], mt[i]);
            float corr = fexp(m[i] - mn);
            p[i][0] = fexp(p[i][0] - mn); p[i][1] = fexp(p[i][1] - mn);
            p[i][2] = fexp(p[i][2] - mn); p[i][3] = fexp(p[i][3] - mn);
            float ls = (p[i][0] + p[i][1]) + (p[i][2] + p[i][3]);
#pragma unroll
            for (int mask = 1; mask < 16; mask <<= 1)
                ls += __shfl_xor_sync(0xffffffff, ls, mask);
            l[i] = l[i] * corr + ls;
            m[i] = mn;
            ULL c2 = d2(corr);
#pragma unroll
            for (int pq = 0; pq < 4; pq++) accO[i][pq] = m2(accO[i][pq], c2);
        }
        __syncthreads();   // done reading spm
        // ---- write P transposed into spm: Pt[key][query] ----
#pragma unroll
        for (int j = 0; j < 4; j++) {
            *(float4*)&spm[(tx * 4 + j) * SPS + ty * 4] =
                make_float4(p[0][j], p[1][j], p[2][j], p[3][j]);
        }
        __syncthreads();
        // ---- PV: keys kk = 4t + ksub ----
#pragma unroll 4
        for (int t = 0; t < 16; t++) {
            int kk = 4 * t + ksub;
            float4 p4 = *(const float4*)&spm[kk * SPS + ty * 4];
            float4 va = *(const float4*)&vsm[kk * VST + d0v];
            float4 vb = *(const float4*)&vsm[kk * VST + d0v + 4];
            ULL v0 = pk(va.x, va.y), v1 = pk(va.z, va.w);
            ULL v2p = pk(vb.x, vb.y), v3 = pk(vb.z, vb.w);
            float pv[4] = {p4.x, p4.y, p4.z, p4.w};
#pragma unroll
            for (int i = 0; i < 4; i++) {
                ULL pd = d2(pv[i]);
                accO[i][0] = f2(pd, v0, accO[i][0]);
                accO[i][1] = f2(pd, v1, accO[i][1]);
                accO[i][2] = f2(pd, v2p, accO[i][2]);
                accO[i][3] = f2(pd, v3, accO[i][3]);
            }
        }
    }

    // ---- reduce over ksub lanes (tid bits 2,3) ----
#pragma unroll
    for (int i = 0; i < 4; i++)
#pragma unroll
        for (int pq = 0; pq < 4; pq++) {
            ULL v = accO[i][pq];
            v = a2(v, __shfl_xor_sync(0xffffffff, v, 4));
            v = a2(v, __shfl_xor_sync(0xffffffff, v, 8));
            accO[i][pq] = v;
        }

    if (ksub == 0) {
#pragma unroll
        for (int i = 0; i < 4; i++) {
            float linv = 1.f / l[i];
            size_t grow = (size_t)(b * NNODE + row0 + ty * 4 + i);
#pragma unroll
            for (int pq = 0; pq < 4; pq++) {
                float2 t = up(accO[i][pq]);
                *(float2*)&o[grow * 256 + h * 32 + d0v + pq * 2] =
                    make_float2(t.x * linv, t.y * linv);
            }
        }
    }
}

// ---------------------------------------------------------------------------
// Launch
// ---------------------------------------------------------------------------
extern "C" void kernel_launch(void* const* d_in, const int* in_sizes, int n_in,
                              void* d_out, int out_size)
{
    const float* x   = (const float*)d_in[0];
    const void*  ei  = d_in[1];
    const float* sph = (const float*)d_in[2];
    const float* Wr  = (const float*)d_in[3];
    const float* Wn  = (const float*)d_in[4];
    const float* Wq  = (const float*)d_in[5];
    const float* bq  = (const float*)d_in[6];
    const float* Wk  = (const float*)d_in[7];
    const float* bk  = (const float*)d_in[8];
    const float* Wv  = (const float*)d_in[9];
    const float* bv  = (const float*)d_in[10];
    const float* Wo  = (const float*)d_in[11];
    const float* bo  = (const float*)d_in[12];
    const float* W1  = (const float*)d_in[13];
    const float* b1  = (const float*)d_in[14];
    const float* W2  = (const float*)d_in[15];
    const float* b2  = (const float*)d_in[16];
    const float* g1  = (const float*)d_in[17];
    const float* be1 = (const float*)d_in[18];
    const float* g2  = (const float*)d_in[19];
    const float* be2 = (const float*)d_in[20];
    const float* g3  = (const float*)d_in[21];
    const float* be3 = (const float*)d_in[22];
    float* out = (float*)d_out;

    float* buf = nullptr;
    cudaGetSymbolAddress((void**)&buf, g_buf);
    float* g_mp     = buf + 0 * (size_t)UNIT;   // [8192,512] msg|pre1
    float* g_h1     = buf + 2 * (size_t)UNIT;
    float* g_qkv    = buf + 3 * (size_t)UNIT;   // [8192,768]
    float* g_o      = buf + 6 * (size_t)UNIT;
    float* g_pre2   = buf + 7 * (size_t)UNIT;
    float* g_out0   = buf + 8 * (size_t)UNIT;
    float* g_out1   = buf + 9 * (size_t)UNIT;
    float* g_hidden = buf + 10 * (size_t)UNIT;  // [8192,512]
    float* g_wrn    = buf + OFF_WRN;
    float* g_wqkv   = buf + OFF_WQKV;
    float* g_bqkv   = buf + OFF_BQKV;
    float* st1      = buf + OFF_STATS;
    float* st2      = st1 + 512;
    float* st3      = st2 + 512;

    dim3 blk(256);

    // 0) edge indices + weight concat + stats zero
    ei_detect_kernel<<<1, 256>>>((const int*)ei);
    ei_convert_kernel<<<(2 * EE + 255) / 256, 256>>>(ei);
    wcat_rn_kernel<<<512, 256>>>(Wn, Wr, g_wrn);
    wcat_qkv_kernel<<<768, 256>>>(Wq, Wk, Wv, bq, bk, bv, g_wqkv, g_bqkv);
    zero_stats_kernel<<<6, 256>>>(st1);

    // 1) local branch: [msg | x@Wr + x] then scatter into cols 256..
    sgemm2<<<dim3(4, 64), blk>>>(x, g_wrn, nullptr, x, 256, 256, g_mp, NB, 512, 256, 0);
    scatter2<<<EE / 4, 256>>>(g_mp);
    bn_stats2<<<128, 256>>>(g_mp, 512, 256, st1);
    bn_apply2<<<2048, 256>>>(g_mp, 512, 256, st1, g1, be1, nullptr, g_h1);

    // 2) attention branch
    sgemm2<<<dim3(6, 64), blk>>>(x, g_wqkv, g_bqkv, nullptr, 0, 0, g_qkv, NB, 768, 256, 0);
    attn2<<<BBATCH * HHEAD * 16, 256>>>(g_qkv, sph, g_o);
    sgemm2<<<dim3(2, 64), blk>>>(g_o, Wo, bo, x, 0, 256, g_pre2, NB, 256, 256, 0);
    bn_stats2<<<128, 256>>>(g_pre2, 256, 0, st2);
    bn_apply2<<<2048, 256>>>(g_pre2, 256, 0, st2, g2, be2, g_h1, g_out0);

    // 3) MLP residual + norm3
    sgemm2<<<dim3(4, 64), blk>>>(g_out0, W1, b1, nullptr, 0, 0, g_hidden, NB, 512, 256, 1);
    sgemm2<<<dim3(2, 64), blk>>>(g_hidden, W2, b2, g_out0, 0, 256, g_out1, NB, 256, 512, 0);
    bn_stats2<<<128, 256>>>(g_out1, 256, 0, st3);
    bn_apply2<<<2048, 256>>>(g_out1, 256, 0, st3, g3, be3, nullptr, out);
}

// round 11
// speedup vs baseline: 3.6863x; 1.0500x over previous
#include <cuda_runtime.h>
#include <cuda_bf16.h>
#include <cstdint>
#include <math.h>

#define NB 8192
#define CC 256
#define EE 131072
#define BBATCH 8
#define NNODE 1024
#define HHEAD 8
#define DKDIM 32
#define EPS 1e-5f

typedef unsigned long long ULL;

// ---------------------------------------------------------------------------
// Scratch
// ---------------------------------------------------------------------------
#define UNIT (8192*256)
// u0-1: mp = [msg | pre1]  (8192 x 512)
// u2: h1   u3-5: qkv (8192x768)   u6: o   u7: pre2   u8: out0   u9: out1
// u10-11: hidden (8192x512)
#define TAIL (12*UNIT)
__device__ float g_buf[12 * UNIT + 331264];
#define OFF_WRN   (TAIL)                  // [256,512]
#define OFF_WQKV  (TAIL + 131072)         // [256,768]
#define OFF_BQKV  (TAIL + 327680)
#define OFF_STATS (TAIL + 328704)

__device__ int g_ei32[2 * EE];
__device__ int g_is64;

// ---------------------------------------------------------------------------
// f32x2 helpers
// ---------------------------------------------------------------------------
__device__ __forceinline__ ULL pk(float a, float b) {
    ULL r; asm("mov.b64 %0, {%1,%2};" : "=l"(r) : "f"(a), "f"(b)); return r;
}
__device__ __forceinline__ ULL d2(float a) {
    ULL r; asm("mov.b64 %0, {%1,%1};" : "=l"(r) : "f"(a)); return r;
}
__device__ __forceinline__ float2 up(ULL a) {
    float2 r; asm("mov.b64 {%0,%1}, %2;" : "=f"(r.x), "=f"(r.y) : "l"(a)); return r;
}
__device__ __forceinline__ ULL f2(ULL a, ULL b, ULL c) {
    ULL d; asm("fma.rn.f32x2 %0, %1, %2, %3;" : "=l"(d) : "l"(a), "l"(b), "l"(c)); return d;
}
__device__ __forceinline__ ULL m2(ULL a, ULL b) {
    ULL d; asm("mul.rn.f32x2 %0, %1, %2;" : "=l"(d) : "l"(a), "l"(b)); return d;
}
__device__ __forceinline__ ULL a2(ULL a, ULL b) {
    ULL d; asm("add.rn.f32x2 %0, %1, %2;" : "=l"(d) : "l"(a), "l"(b)); return d;
}
__device__ __forceinline__ float fexp(float x) {
    x = fmaxf(x, -80.f);
    float y = x * 1.4426950408889634f;
    float z = y + 12582912.f;
    int ni = __float_as_int(z);
    float nf = z - 12582912.f;
    float t = (y - nf) * 0.6931471805599453f;
    float p = 1.f + t * (1.f + t * (0.5f + t * (0.16666667f + t * (0.041666667f + t * 0.0083333333f))));
    float sc = __int_as_float((ni + 127) << 23);
    return p * sc;
}

// ---------------------------------------------------------------------------
// Edge-index dtype detection + conversion
// ---------------------------------------------------------------------------
__global__ void ei_detect_kernel(const int* __restrict__ raw)
{
    __shared__ int nz;
    if (threadIdx.x == 0) nz = 0;
    __syncthreads();
    if (raw[2 * threadIdx.x + 1] != 0) atomicAdd(&nz, 1);
    __syncthreads();
    if (threadIdx.x == 0) g_is64 = (nz == 0) ? 1 : 0;
}

__global__ void ei_convert_kernel(const void* __restrict__ raw)
{
    int i = blockIdx.x * blockDim.x + threadIdx.x;
    if (i >= 2 * EE) return;
    int v;
    if (g_is64) v = (int)((const long long*)raw)[i];
    else        v = ((const int*)raw)[i];
    g_ei32[i] = min(max(v, 0), NB - 1);
}

// ---------------------------------------------------------------------------
// Weight concat kernels
// ---------------------------------------------------------------------------
__global__ void wcat_rn_kernel(const float* __restrict__ Wn, const float* __restrict__ Wr,
                               float* __restrict__ W)
{
    int idx = blockIdx.x * 256 + threadIdx.x;   // 0..131071
    int r = idx >> 9, c = idx & 511;
    W[idx] = (c < 256) ? Wn[r * 256 + c] : Wr[r * 256 + (c - 256)];
}

__global__ void wcat_qkv_kernel(const float* __restrict__ Wq, const float* __restrict__ Wk,
                                const float* __restrict__ Wv,
                                const float* __restrict__ bq, const float* __restrict__ bk,
                                const float* __restrict__ bv,
                                float* __restrict__ W, float* __restrict__ bvec)
{
    int idx = blockIdx.x * 256 + threadIdx.x;   // 0..196607
    int r = idx / 768, c = idx % 768;
    int sel = c >> 8, cc = c & 255;
    const float* src = (sel == 0) ? Wq : (sel == 1) ? Wk : Wv;
    W[idx] = src[r * 256 + cc];
    if (idx < 768) {
        const float* bs = (sel == 0) ? bq : (sel == 1) ? bk : bv;
        bvec[idx] = bs[idx & 255];
    }
}

__global__ void zero_stats_kernel(float* stats) {
    stats[blockIdx.x * 256 + threadIdx.x] = 0.f;   // grid 6 -> 1536 floats
}

// ---------------------------------------------------------------------------
// SGEMM with f32x2 + double buffering. 128x128 tile, BK=8, 256 threads.
// ---------------------------------------------------------------------------
__global__ __launch_bounds__(256) void sgemm2(
    const float* __restrict__ X, const float* __restrict__ W,
    const float* __restrict__ bias, const float* __restrict__ add,
    int addOff, int addStride,
    float* __restrict__ Y, int M, int N, int K, int relu)
{
    __shared__ float Xs[2][8][128];
    __shared__ float Ws[2][8][128];
    int tid = threadIdx.x;
    int tx = tid & 15, ty = tid >> 4;
    int row0 = blockIdx.y * 128, col0 = blockIdx.x * 128;

    int lm = tid >> 1, lh = (tid & 1) * 4;
    int lk = tid >> 5, ln = (tid & 31) * 4;
    const float* Xp = X + (size_t)(row0 + lm) * K + lh;
    const float* Wp = W + (size_t)lk * N + col0 + ln;

    ULL acc[8][4];
#pragma unroll
    for (int i = 0; i < 8; i++)
#pragma unroll
        for (int j = 0; j < 4; j++) acc[i][j] = 0ULL;

    {
        float4 xa = *(const float4*)(Xp);
        Xs[0][lh + 0][lm] = xa.x; Xs[0][lh + 1][lm] = xa.y;
        Xs[0][lh + 2][lm] = xa.z; Xs[0][lh + 3][lm] = xa.w;
        *(float4*)&Ws[0][lk][ln] = *(const float4*)(Wp);
    }
    __syncthreads();

    int buf = 0;
    for (int k0 = 0; k0 < K; k0 += 8) {
        if (k0 + 8 < K) {
            float4 xa = *(const float4*)(Xp + k0 + 8);
            Xs[buf ^ 1][lh + 0][lm] = xa.x; Xs[buf ^ 1][lh + 1][lm] = xa.y;
            Xs[buf ^ 1][lh + 2][lm] = xa.z; Xs[buf ^ 1][lh + 3][lm] = xa.w;
            *(float4*)&Ws[buf ^ 1][lk][ln] = *(const float4*)(Wp + (size_t)(k0 + 8) * N);
        }
#pragma unroll
        for (int kk = 0; kk < 8; kk++) {
            float4 a0 = *(const float4*)&Xs[buf][kk][ty * 4];
            float4 a1 = *(const float4*)&Xs[buf][kk][64 + ty * 4];
            float4 b0 = *(const float4*)&Ws[buf][kk][tx * 4];
            float4 b1 = *(const float4*)&Ws[buf][kk][64 + tx * 4];
            // B pairs come free: float4 from LDS.128 is 4 consecutive regs
            ULL bp0 = *reinterpret_cast<ULL*>(&b0.x);
            ULL bp1 = *reinterpret_cast<ULL*>(&b0.z);
            ULL bp2 = *reinterpret_cast<ULL*>(&b1.x);
            ULL bp3 = *reinterpret_cast<ULL*>(&b1.z);
            float av[8] = {a0.x, a0.y, a0.z, a0.w, a1.x, a1.y, a1.z, a1.w};
#pragma unroll
            for (int i = 0; i < 8; i++) {
                ULL ad = d2(av[i]);
                acc[i][0] = f2(ad, bp0, acc[i][0]);
                acc[i][1] = f2(ad, bp1, acc[i][1]);
                acc[i][2] = f2(ad, bp2, acc[i][2]);
                acc[i][3] = f2(ad, bp3, acc[i][3]);
            }
        }
        __syncthreads();
        buf ^= 1;
    }

#pragma unroll
    for (int i = 0; i < 8; i++) {
        int r = row0 + ((i < 4) ? (ty * 4 + i) : (64 + ty * 4 + i - 4));
#pragma unroll
        for (int jp = 0; jp < 4; jp++) {
            int c = col0 + ((jp < 2) ? (tx * 4 + jp * 2) : (64 + tx * 4 + (jp - 2) * 2));
            float2 t = up(acc[i][jp]);
            float v0 = t.x, v1 = t.y;
            if (bias) { v0 += bias[c]; v1 += bias[c + 1]; }
            if (add && c >= addOff) {
                v0 += add[(size_t)r * addStride + (c - addOff)];
                v1 += add[(size_t)r * addStride + (c + 1 - addOff)];
            }
            if (relu) { v0 = fmaxf(v0, 0.f); v1 = fmaxf(v1, 0.f); }
            *(float2*)&Y[(size_t)r * N + c] = make_float2(v0, v1);
        }
    }
}

// ---------------------------------------------------------------------------
// Edge scatter: mp[dst, 256+c] += mp[src, c]
// ---------------------------------------------------------------------------
__global__ __launch_bounds__(256) void scatter2(float* __restrict__ mp)
{
    int u = threadIdx.x >> 6;
    int c4 = (threadIdx.x & 63) * 4;
    int e = blockIdx.x * 4 + u;
    int s = g_ei32[e], d = g_ei32[EE + e];
    float4 v = *(const float4*)&mp[(size_t)s * 512 + c4];
    float* p = &mp[(size_t)d * 512 + 256 + c4];
    asm volatile("red.global.add.v4.f32 [%0], {%1,%2,%3,%4};"
                 :: "l"(p), "f"(v.x), "f"(v.y), "f"(v.z), "f"(v.w) : "memory");
}

// ---------------------------------------------------------------------------
// BatchNorm
// ---------------------------------------------------------------------------
__global__ __launch_bounds__(256) void bn_stats2(const float* __restrict__ X,
                                                 int stride, int coloff,
                                                 float* __restrict__ stats)
{
    __shared__ float4 rs[4][64], rq[4][64];
    int tid = threadIdx.x;
    int cg = tid & 63, g = tid >> 6;
    int c4 = cg * 4;
    int r0 = blockIdx.x * 64;
    float4 s = make_float4(0, 0, 0, 0), q = make_float4(0, 0, 0, 0);
    for (int r = g; r < 64; r += 4) {
        float4 v = *(const float4*)&X[(size_t)(r0 + r) * stride + coloff + c4];
        s.x += v.x; s.y += v.y; s.z += v.z; s.w += v.w;
        q.x += v.x * v.x; q.y += v.y * v.y; q.z += v.z * v.z; q.w += v.w * v.w;
    }
    rs[g][cg] = s; rq[g][cg] = q;
    __syncthreads();
    if (g == 0) {
        float4 S = rs[0][cg], Q = rq[0][cg];
#pragma unroll
        for (int i = 1; i < 4; i++) {
            float4 a = rs[i][cg], b = rq[i][cg];
            S.x += a.x; S.y += a.y; S.z += a.z; S.w += a.w;
            Q.x += b.x; Q.y += b.y; Q.z += b.z; Q.w += b.w;
        }
        atomicAdd(&stats[c4 + 0], S.x); atomicAdd(&stats[c4 + 1], S.y);
        atomicAdd(&stats[c4 + 2], S.z); atomicAdd(&stats[c4 + 3], S.w);
        atomicAdd(&stats[256 + c4 + 0], Q.x); atomicAdd(&stats[256 + c4 + 1], Q.y);
        atomicAdd(&stats[256 + c4 + 2], Q.z); atomicAdd(&stats[256 + c4 + 3], Q.w);
    }
}

__global__ __launch_bounds__(256) void bn_apply2(const float* __restrict__ X,
                                                 int stride, int coloff,
                                                 const float* __restrict__ stats,
                                                 const float* __restrict__ gamma,
                                                 const float* __restrict__ beta,
                                                 const float* __restrict__ add,
                                                 float* __restrict__ Y)
{
    int idx = blockIdx.x * 256 + threadIdx.x;
    int r = idx >> 6, c4 = (idx & 63) * 4;
    float4 v = *(const float4*)&X[(size_t)r * stride + coloff + c4];
    float4 S = *(const float4*)&stats[c4];
    float4 Q = *(const float4*)&stats[256 + c4];
    float4 G = *(const float4*)&gamma[c4];
    float4 Bt = *(const float4*)&beta[c4];
    const float invN = 1.f / NB;
    float m0 = S.x * invN, m1 = S.y * invN, m2v = S.z * invN, m3 = S.w * invN;
    float i0 = rsqrtf(Q.x * invN - m0 * m0 + EPS);
    float i1 = rsqrtf(Q.y * invN - m1 * m1 + EPS);
    float i2 = rsqrtf(Q.z * invN - m2v * m2v + EPS);
    float i3 = rsqrtf(Q.w * invN - m3 * m3 + EPS);
    float4 o;
    o.x = (v.x - m0) * i0 * G.x + Bt.x;
    o.y = (v.y - m1) * i1 * G.y + Bt.y;
    o.z = (v.z - m2v) * i2 * G.z + Bt.z;
    o.w = (v.w - m3) * i3 * G.w + Bt.w;
    if (add) {
        float4 a = *(const float4*)&add[(size_t)r * 256 + c4];
        o.x += a.x; o.y += a.y; o.z += a.z; o.w += a.w;
    }
    *(float4*)&Y[(size_t)r * 256 + c4] = o;
}

// ---------------------------------------------------------------------------
// Attention: f32x2 outer-product flash with sph modulation
// ---------------------------------------------------------------------------
#define QTS 68
#define VST 36
#define SPS 68

__global__ __launch_bounds__(256, 2) void attn2(const float* __restrict__ qkv,
                                                const float* __restrict__ sph,
                                                float* __restrict__ o)
{
    __shared__ float qt[32 * QTS];
    __shared__ float ktile[32 * QTS];
    __shared__ float vsm[64 * VST];
    __shared__ float spm[64 * SPS];

    int tid = threadIdx.x;
    int bh = blockIdx.x >> 4;
    int qti = blockIdx.x & 15;
    int b = bh >> 3, h = bh & 7;
    int row0 = qti * 64;
    const float scale = 0.17677669529663687f;

    {
        int r = tid >> 2, cq = tid & 3;
        const float* qrow = qkv + (size_t)(b * NNODE + row0 + r) * 768 + h * 32 + cq * 8;
        float4 qa = *(const float4*)qrow;
        float4 qb = *(const float4*)(qrow + 4);
        int d0 = cq * 8;
        qt[(d0 + 0) * QTS + r] = qa.x * scale; qt[(d0 + 1) * QTS + r] = qa.y * scale;
        qt[(d0 + 2) * QTS + r] = qa.z * scale; qt[(d0 + 3) * QTS + r] = qa.w * scale;
        qt[(d0 + 4) * QTS + r] = qb.x * scale; qt[(d0 + 5) * QTS + r] = qb.y * scale;
        qt[(d0 + 6) * QTS + r] = qb.z * scale; qt[(d0 + 7) * QTS + r] = qb.w * scale;
    }

    int ty = tid >> 4, tx = tid & 15;
    int dg = tid & 3, ksub = (tid >> 2) & 3;
    int d0v = dg * 8;

    float m[4], l[4];
#pragma unroll
    for (int i = 0; i < 4; i++) { m[i] = -INFINITY; l[i] = 0.f; }
    ULL accO[4][4];
#pragma unroll
    for (int i = 0; i < 4; i++)
#pragma unroll
        for (int p = 0; p < 4; p++) accO[i][p] = 0ULL;

    for (int kt0 = 0; kt0 < NNODE; kt0 += 64) {
        __syncthreads();
        {
            int r = tid >> 2, cq = tid & 3;
            const float* krow = qkv + (size_t)(b * NNODE + kt0 + r) * 768 + 256 + h * 32 + cq * 8;
            float4 ka = *(const float4*)krow;
            float4 kb = *(const float4*)(krow + 4);
            int d0 = cq * 8;
            ktile[(d0 + 0) * QTS + r] = ka.x; ktile[(d0 + 1) * QTS + r] = ka.y;
            ktile[(d0 + 2) * QTS + r] = ka.z; ktile[(d0 + 3) * QTS + r] = ka.w;
            ktile[(d0 + 4) * QTS + r] = kb.x; ktile[(d0 + 5) * QTS + r] = kb.y;
            ktile[(d0 + 6) * QTS + r] = kb.z; ktile[(d0 + 7) * QTS + r] = kb.w;
            const float* vrow = qkv + (size_t)(b * NNODE + kt0 + r) * 768 + 512 + h * 32 + cq * 8;
            *(float4*)&vsm[r * VST + cq * 8]     = *(const float4*)vrow;
            *(float4*)&vsm[r * VST + cq * 8 + 4] = *(const float4*)(vrow + 4);
        }
#pragma unroll
        for (int it = 0; it < 4; it++) {
            int idx = it * 256 + tid;
            int qr = idx >> 4, kc4 = (idx & 15) * 4;
            *(float4*)&spm[qr * SPS + kc4] =
                *(const float4*)&sph[((size_t)(b * NNODE + row0 + qr)) * NNODE + kt0 + kc4];
        }
        __syncthreads();

        ULL s2[4][2];
#pragma unroll
        for (int i = 0; i < 4; i++) { s2[i][0] = 0ULL; s2[i][1] = 0ULL; }
#pragma unroll 8
        for (int d = 0; d < 32; d++) {
            float4 q4 = *(const float4*)&qt[d * QTS + ty * 4];
            float4 k4 = *(const float4*)&ktile[d * QTS + tx * 4];
            ULL k01 = *reinterpret_cast<ULL*>(&k4.x);
            ULL k23 = *reinterpret_cast<ULL*>(&k4.z);
            float qv[4] = {q4.x, q4.y, q4.z, q4.w};
#pragma unroll
            for (int i = 0; i < 4; i++) {
                ULL qd = d2(qv[i]);
                s2[i][0] = f2(qd, k01, s2[i][0]);
                s2[i][1] = f2(qd, k23, s2[i][1]);
            }
        }

        float p[4][4], mt[4];
#pragma unroll
        for (int i = 0; i < 4; i++) {
            float4 sp4 = *(const float4*)&spm[(ty * 4 + i) * SPS + tx * 4];
            float2 ua = up(s2[i][0]), ub = up(s2[i][1]);
            p[i][0] = ua.x * sp4.x; p[i][1] = ua.y * sp4.y;
            p[i][2] = ub.x * sp4.z; p[i][3] = ub.y * sp4.w;
            mt[i] = fmaxf(fmaxf(p[i][0], p[i][1]), fmaxf(p[i][2], p[i][3]));
        }
#pragma unroll
        for (int mask = 1; mask < 16; mask <<= 1)
#pragma unroll
            for (int i = 0; i < 4; i++)
                mt[i] = fmaxf(mt[i], __shfl_xor_sync(0xffffffff, mt[i], mask));
#pragma unroll
        for (int i = 0; i < 4; i++) {
            float mn = fmaxf(m[i], mt[i]);
            float corr = fexp(m[i] - mn);
            p[i][0] = fexp(p[i][0] - mn); p[i][1] = fexp(p[i][1] - mn);
            p[i][2] = fexp(p[i][2] - mn); p[i][3] = fexp(p[i][3] - mn);
            float ls = (p[i][0] + p[i][1]) + (p[i][2] + p[i][3]);
#pragma unroll
            for (int mask = 1; mask < 16; mask <<= 1)
                ls += __shfl_xor_sync(0xffffffff, ls, mask);
            l[i] = l[i] * corr + ls;
            m[i] = mn;
            ULL c2 = d2(corr);
#pragma unroll
            for (int pq = 0; pq < 4; pq++) accO[i][pq] = m2(accO[i][pq], c2);
        }
        __syncthreads();
#pragma unroll
        for (int j = 0; j < 4; j++) {
            *(float4*)&spm[(tx * 4 + j) * SPS + ty * 4] =
                make_float4(p[0][j], p[1][j], p[2][j], p[3][j]);
        }
        __syncthreads();
#pragma unroll 4
        for (int t = 0; t < 16; t++) {
            int kk = 4 * t + ksub;
            float4 p4 = *(const float4*)&spm[kk * SPS + ty * 4];
            float4 va = *(const float4*)&vsm[kk * VST + d0v];
            float4 vb = *(const float4*)&vsm[kk * VST + d0v + 4];
            ULL v0 = *reinterpret_cast<ULL*>(&va.x);
            ULL v1 = *reinterpret_cast<ULL*>(&va.z);
            ULL v2p = *reinterpret_cast<ULL*>(&vb.x);
            ULL v3 = *reinterpret_cast<ULL*>(&vb.z);
            float pv[4] = {p4.x, p4.y, p4.z, p4.w};
#pragma unroll
            for (int i = 0; i < 4; i++) {
                ULL pd = d2(pv[i]);
                accO[i][0] = f2(pd, v0, accO[i][0]);
                accO[i][1] = f2(pd, v1, accO[i][1]);
                accO[i][2] = f2(pd, v2p, accO[i][2]);
                accO[i][3] = f2(pd, v3, accO[i][3]);
            }
        }
    }

#pragma unroll
    for (int i = 0; i < 4; i++)
#pragma unroll
        for (int pq = 0; pq < 4; pq++) {
            ULL v = accO[i][pq];
            v = a2(v, __shfl_xor_sync(0xffffffff, v, 4));
            v = a2(v, __shfl_xor_sync(0xffffffff, v, 8));
            accO[i][pq] = v;
        }

    if (ksub == 0) {
#pragma unroll
        for (int i = 0; i < 4; i++) {
            float linv = 1.f / l[i];
            size_t grow = (size_t)(b * NNODE + row0 + ty * 4 + i);
#pragma unroll
            for (int pq = 0; pq < 4; pq++) {
                float2 t = up(accO[i][pq]);
                *(float2*)&o[grow * 256 + h * 32 + d0v + pq * 2] =
                    make_float2(t.x * linv, t.y * linv);
            }
        }
    }
}

// ---------------------------------------------------------------------------
// Launch — graph-forked dual stream: local branch overlaps attention branch
// ---------------------------------------------------------------------------
static cudaStream_t g_s1 = nullptr;
static cudaEvent_t g_ev0 = nullptr, g_ev1 = nullptr;

extern "C" void kernel_launch(void* const* d_in, const int* in_sizes, int n_in,
                              void* d_out, int out_size)
{
    const float* x   = (const float*)d_in[0];
    const void*  ei  = d_in[1];
    const float* sph = (const float*)d_in[2];
    const float* Wr  = (const float*)d_in[3];
    const float* Wn  = (const float*)d_in[4];
    const float* Wq  = (const float*)d_in[5];
    const float* bq  = (const float*)d_in[6];
    const float* Wk  = (const float*)d_in[7];
    const float* bk  = (const float*)d_in[8];
    const float* Wv  = (const float*)d_in[9];
    const float* bv  = (const float*)d_in[10];
    const float* Wo  = (const float*)d_in[11];
    const float* bo  = (const float*)d_in[12];
    const float* W1  = (const float*)d_in[13];
    const float* b1  = (const float*)d_in[14];
    const float* W2  = (const float*)d_in[15];
    const float* b2  = (const float*)d_in[16];
    const float* g1  = (const float*)d_in[17];
    const float* be1 = (const float*)d_in[18];
    const float* g2  = (const float*)d_in[19];
    const float* be2 = (const float*)d_in[20];
    const float* g3  = (const float*)d_in[21];
    const float* be3 = (const float*)d_in[22];
    float* out = (float*)d_out;

    float* buf = nullptr;
    cudaGetSymbolAddress((void**)&buf, g_buf);
    float* g_mp     = buf + 0 * (size_t)UNIT;   // [8192,512] msg|pre1
    float* g_h1     = buf + 2 * (size_t)UNIT;
    float* g_qkv    = buf + 3 * (size_t)UNIT;   // [8192,768]
    float* g_o      = buf + 6 * (size_t)UNIT;
    float* g_pre2   = buf + 7 * (size_t)UNIT;
    float* g_out0   = buf + 8 * (size_t)UNIT;
    float* g_out1   = buf + 9 * (size_t)UNIT;
    float* g_hidden = buf + 10 * (size_t)UNIT;  // [8192,512]
    float* g_wrn    = buf + OFF_WRN;
    float* g_wqkv   = buf + OFF_WQKV;
    float* g_bqkv   = buf + OFF_BQKV;
    float* st1      = buf + OFF_STATS;
    float* st2      = st1 + 512;
    float* st3      = st2 + 512;

    // Lazy one-time creation (pre-capture on the correctness call); no device
    // memory involved, identical launch sequence on every call.
    if (!g_s1) {
        cudaStreamCreateWithFlags(&g_s1, cudaStreamNonBlocking);
        cudaEventCreateWithFlags(&g_ev0, cudaEventDisableTiming);
        cudaEventCreateWithFlags(&g_ev1, cudaEventDisableTiming);
    }
    bool fork = (g_s1 != nullptr && g_ev0 != nullptr && g_ev1 != nullptr);
    cudaStream_t sLocal = fork ? g_s1 : (cudaStream_t)0;

    dim3 blk(256);

    // 0) prep (default stream)
    ei_detect_kernel<<<1, 256>>>((const int*)ei);
    ei_convert_kernel<<<(2 * EE + 255) / 256, 256>>>(ei);
    wcat_rn_kernel<<<512, 256>>>(Wn, Wr, g_wrn);
    wcat_qkv_kernel<<<768, 256>>>(Wq, Wk, Wv, bq, bk, bv, g_wqkv, g_bqkv);
    zero_stats_kernel<<<6, 256>>>(st1);

    // fork: local branch on sLocal
    if (fork) {
        cudaEventRecord(g_ev0, 0);
        cudaStreamWaitEvent(g_s1, g_ev0, 0);
    }

    // 1) local branch: [msg | x@Wr + x], scatter into cols 256.., bn -> h1
    sgemm2<<<dim3(4, 64), blk, 0, sLocal>>>(x, g_wrn, nullptr, x, 256, 256, g_mp, NB, 512, 256, 0);
    scatter2<<<EE / 4, 256, 0, sLocal>>>(g_mp);
    bn_stats2<<<128, 256, 0, sLocal>>>(g_mp, 512, 256, st1);
    bn_apply2<<<2048, 256, 0, sLocal>>>(g_mp, 512, 256, st1, g1, be1, nullptr, g_h1);
    if (fork) cudaEventRecord(g_ev1, g_s1);

    // 2) attention branch (default stream, concurrent with local branch)
    sgemm2<<<dim3(6, 64), blk>>>(x, g_wqkv, g_bqkv, nullptr, 0, 0, g_qkv, NB, 768, 256, 0);
    attn2<<<BBATCH * HHEAD * 16, 256>>>(g_qkv, sph, g_o);
    sgemm2<<<dim3(2, 64), blk>>>(g_o, Wo, bo, x, 0, 256, g_pre2, NB, 256, 256, 0);
    bn_stats2<<<128, 256>>>(g_pre2, 256, 0, st2);

    // join: out0 = bn(pre2) + h1
    if (fork) cudaStreamWaitEvent((cudaStream_t)0, g_ev1, 0);
    bn_apply2<<<2048, 256>>>(g_pre2, 256, 0, st2, g2, be2, g_h1, g_out0);

    // 3) MLP residual + norm3
    sgemm2<<<dim3(4, 64), blk>>>(g_out0, W1, b1, nullptr, 0, 0, g_hidden, NB, 512, 256, 1);
    sgemm2<<<dim3(2, 64), blk>>>(g_hidden, W2, b2, g_out0, 0, 256, g_out1, NB, 256, 512, 0);
    bn_stats2<<<128, 256>>>(g_out1, 256, 0, st3);
    bn_apply2<<<2048, 256>>>(g_out1, 256, 0, st3, g3, be3, nullptr, out);
}